// round 17
// baseline (speedup 1.0000x reference)
#include <cuda_runtime.h>
#include <cuda_fp16.h>
#include <cstdint>
#include <math.h>

#define NBATCH 2
#define SEQ    4096
#define EMB    1024
#define FFDIM  4096
#define MROWS  (NBATCH*SEQ)   // 8192

typedef __half h16;

// ---------------- scratch (device globals; allocation-free) ----------------
__device__ h16 qin_h[MROWS*EMB];
__device__ h16 kin_h[MROWS*EMB];
__device__ h16 vin_h[MROWS*EMB];
__device__ h16 wq_h[EMB*EMB];
__device__ h16 wk_h[EMB*EMB];
__device__ h16 wv_h[EMB*EMB];
__device__ h16 w1_h[FFDIM*EMB];
__device__ h16 w2_h[EMB*FFDIM];
__device__ h16 q_h[MROWS*EMB];
__device__ h16 k_h[MROWS*EMB];
__device__ h16 vt_h[NBATCH*EMB*SEQ];
__device__ h16 at_h[(size_t)NBATCH*SEQ*SEQ];
__device__ h16 x_h[MROWS*EMB];
__device__ h16 h_h[MROWS*FFDIM];
__device__ float g_attnf[(size_t)NBATCH*SEQ*SEQ];
__device__ float g_x[MROWS*EMB];
__device__ float g_y[MROWS*EMB];

// ---------------- helpers ----------------
__device__ __forceinline__ uint32_t smem_u32(const void* p) {
    uint32_t a;
    asm("{ .reg .u64 t; cvta.to.shared.u64 t, %1; cvt.u32.u64 %0, t; }" : "=r"(a) : "l"(p));
    return a;
}
__device__ __forceinline__ void ldsm4(uint32_t r[4], uint32_t addr) {
    asm volatile("ldmatrix.sync.aligned.m8n8.x4.shared.b16 {%0,%1,%2,%3}, [%4];"
                 : "=r"(r[0]), "=r"(r[1]), "=r"(r[2]), "=r"(r[3]) : "r"(addr));
}
__device__ __forceinline__ void mma_f32(float c[4], const uint32_t a[4],
                                        uint32_t b0, uint32_t b1) {
    asm volatile("mma.sync.aligned.m16n8k16.row.col.f32.f16.f16.f32 "
                 "{%0,%1,%2,%3}, {%4,%5,%6,%7}, {%8,%9}, {%0,%1,%2,%3};"
                 : "+f"(c[0]), "+f"(c[1]), "+f"(c[2]), "+f"(c[3])
                 : "r"(a[0]), "r"(a[1]), "r"(a[2]), "r"(a[3]), "r"(b0), "r"(b1));
}
__device__ __forceinline__ void cpasync16(uint32_t dst, const void* src) {
    asm volatile("cp.async.cg.shared.global [%0], [%1], 16;" :: "r"(dst), "l"(src) : "memory");
}
#define CP_COMMIT() asm volatile("cp.async.commit_group;" ::: "memory")
#define CP_WAIT(n)  asm volatile("cp.async.wait_group %0;" :: "n"(n) : "memory")

// fp32x4 -> fp16x4 (uint2)
__device__ __forceinline__ uint2 h4cvt(const float4& f) {
    __half2 h01 = __floats2half2_rn(f.x, f.y);
    __half2 h23 = __floats2half2_rn(f.z, f.w);
    uint2 H;
    H.x = *reinterpret_cast<uint32_t*>(&h01);
    H.y = *reinterpret_cast<uint32_t*>(&h23);
    return H;
}

// ---------------- elementwise converter: hi = fp16(a [+ b]) ----------------
__global__ void __launch_bounds__(256)
cvt_h(const float* __restrict__ a, const float* __restrict__ b, h16* __restrict__ hi)
{
    const size_t i4 = ((size_t)blockIdx.x * 256 + threadIdx.x) * 4;
    float4 f = *(const float4*)(a + i4);
    if (b) {
        const float4 e = *(const float4*)(b + i4);
        f.x += e.x; f.y += e.y; f.z += e.z; f.w += e.w;
    }
    *(uint2*)(hi + i4) = h4cvt(f);
}

// ================= BIG GEMM: CTA 256x128, 512 thr, K-chunk 128, NS=2 =========
#define NS 2
#define A_SUB   32768
#define A_STAGE 65536
#define B_SUB   16384
#define STAGE_BYTES 98304
#define EPI_PITCH   132
#define EPI_PITCH_T 260
#define SMEM_TOTAL  (NS*STAGE_BYTES)    // 196608
#define NTHR 512

template<int OP, bool OUTF, bool OUTB, bool TRANS>
__global__ void __launch_bounds__(NTHR)
hmma_gemm(const h16* __restrict__ Ahi, const h16* __restrict__ Bhi,
          const float* __restrict__ bias,
          float* __restrict__ Cf, h16* __restrict__ Chi,
          int K, int ldC, size_t sA, size_t sB, size_t sC, float scale)
{
    extern __shared__ char smem[];
    const uint32_t sbase = smem_u32(smem);

    const int t = threadIdx.x;
    const int w = t >> 5, lane = t & 31;
    const int wm = w >> 2, wn = w & 3;            // warp grid 4 x 4

    const int bz = blockIdx.z;
    Ahi += (size_t)bz * sA;
    Bhi += (size_t)bz * sB;
    const int mBase = blockIdx.y * 256;
    const int nBase = blockIdx.x * 128;

    float accF[4][4][4];
    #pragma unroll
    for (int mi = 0; mi < 4; mi++)
        #pragma unroll
        for (int nj = 0; nj < 4; nj++)
            #pragma unroll
            for (int e = 0; e < 4; e++) accF[mi][nj][e] = 0.f;

    const int nk = K >> 7;

    const int arow = t >> 1;
    const uint32_t arx = ((uint32_t)(arow & 7)) << 4;
    const uint32_t arowoff = (uint32_t)arow * 128;
    const int brow = t >> 2;
    const uint32_t brx = ((uint32_t)(brow & 7)) << 4;
    const uint32_t browoff = (uint32_t)brow * 128;
    const size_t gArow = (size_t)(mBase + arow) * K;
    const size_t gBrow = (size_t)(nBase + brow) * K;

    auto ISSUE = [&](int kc, int s) {
        const int kb = kc << 7;
        const uint32_t st = sbase + (uint32_t)s * STAGE_BYTES;
        #pragma unroll
        for (int h = 0; h < 2; h++) {
            const int kh = kb + h * 64;
            #pragma unroll
            for (int c = 0; c < 4; c++) {
                const int col16 = (t & 1) * 4 + c;
                const uint32_t d = arowoff + (((uint32_t)col16 * 16) ^ arx);
                cpasync16(st + h * A_SUB + d, Ahi + gArow + kh + col16 * 8);
            }
            #pragma unroll
            for (int c = 0; c < 2; c++) {
                const int col16 = (t & 3) * 2 + c;
                const uint32_t d = browoff + (((uint32_t)col16 * 16) ^ brx);
                cpasync16(st + A_STAGE + h * B_SUB + d, Bhi + gBrow + kh + col16 * 8);
            }
        }
    };

    const uint32_t arow128 = (uint32_t)(wm * 64 + (lane & 15)) * 128;
    const uint32_t a16     = ((uint32_t)(lane >> 4)) << 4;
    const uint32_t axor    = ((uint32_t)(lane & 7)) << 4;
    const uint32_t brow128 = (uint32_t)(wn * 32 + ((lane >> 4) << 3) + (lane & 7)) * 128;
    const uint32_t b16     = ((uint32_t)((lane >> 3) & 1)) << 4;

    auto COMPUTE = [&](int s) {
        const uint32_t st = sbase + (uint32_t)s * STAGE_BYTES;
        #pragma unroll
        for (int h = 0; h < 2; h++) {
            const uint32_t stA = st + h * A_SUB;
            const uint32_t stB = st + A_STAGE + h * B_SUB;
            #pragma unroll
            for (int ki = 0; ki < 4; ki++) {
                const uint32_t kba = (uint32_t)(ki * 32);
                uint32_t Af[4][4], Bf[4][2];
                #pragma unroll
                for (int mi = 0; mi < 4; mi++)
                    ldsm4(Af[mi], stA + arow128 + mi * 2048 + ((kba + a16) ^ axor));
                #pragma unroll
                for (int nx = 0; nx < 2; nx++) {
                    uint32_t tb[4];
                    ldsm4(tb, stB + brow128 + nx * 2048 + ((kba + b16) ^ axor));
                    Bf[nx*2][0]   = tb[0]; Bf[nx*2][1]   = tb[1];
                    Bf[nx*2+1][0] = tb[2]; Bf[nx*2+1][1] = tb[3];
                }
                #pragma unroll
                for (int nj = 0; nj < 4; nj++)
                    #pragma unroll
                    for (int mi = 0; mi < 4; mi++)
                        mma_f32(accF[mi][nj], Af[mi], Bf[nj][0], Bf[nj][1]);
            }
        }
    };

    ISSUE(0, 0);
    CP_COMMIT();
    for (int kc = 0; kc < nk; kc++) {
        CP_WAIT(0);
        __syncthreads();
        if (kc + 1 < nk) { ISSUE(kc + 1, (kc + 1) & 1); CP_COMMIT(); }
        COMPUTE(kc & 1);
    }
    __syncthreads();

    float* epi = (float*)smem;
    const int g  = lane >> 2;
    const int tq = lane & 3;
    #pragma unroll
    for (int mi = 0; mi < 4; mi++) {
        #pragma unroll
        for (int nj = 0; nj < 4; nj++) {
            const int col = wn * 32 + nj * 8 + tq * 2;
            #pragma unroll
            for (int half = 0; half < 2; half++) {
                const int m = wm * 64 + mi * 16 + g + half * 8;
                float v0 = accF[mi][nj][half*2 + 0];
                float v1 = accF[mi][nj][half*2 + 1];
                if (OP == 2) {
                    v0 = 1.f / (1.f + __expf(-v0 * scale));
                    v1 = 1.f / (1.f + __expf(-v1 * scale));
                } else {
                    if (bias) { v0 += bias[nBase + col]; v1 += bias[nBase + col + 1]; }
                    if (OP == 1) { v0 = fmaxf(v0, 0.f); v1 = fmaxf(v1, 0.f); }
                }
                if (TRANS) {
                    epi[(col)     * EPI_PITCH_T + m] = v0;
                    epi[(col + 1) * EPI_PITCH_T + m] = v1;
                } else {
                    epi[m * EPI_PITCH + col]     = v0;
                    epi[m * EPI_PITCH + col + 1] = v1;
                }
            }
        }
    }
    __syncthreads();

    if (TRANS) {
        const int r  = t >> 2;
        const int ch = (t & 3) * 64;
        const size_t boffs = (size_t)(mBase >> 12) * ((size_t)EMB * SEQ);
        const size_t rowOff = boffs + (size_t)(nBase + r) * SEQ + (size_t)(mBase & (SEQ - 1)) + ch;
        #pragma unroll
        for (int i = 0; i < 16; i++) {
            const float* e = &epi[r * EPI_PITCH_T + ch + i * 4];
            const float4 f = make_float4(e[0], e[1], e[2], e[3]);
            if (OUTF) *(float4*)(Cf + rowOff + i * 4) = f;
            if (OUTB) *(uint2*)(Chi + rowOff + i * 4) = h4cvt(f);
        }
    } else {
        const int r  = t >> 1;
        const int ch = (t & 1) * 64;
        const size_t rowOff = (size_t)bz * sC + (size_t)(mBase + r) * ldC + nBase + ch;
        #pragma unroll
        for (int i = 0; i < 16; i++) {
            const float* e = &epi[r * EPI_PITCH + ch + i * 4];
            const float4 f = make_float4(e[0], e[1], e[2], e[3]);
            if (OUTF) *(float4*)(Cf + rowOff + i * 4) = f;
            if (OUTB) *(uint2*)(Chi + rowOff + i * 4) = h4cvt(f);
        }
    }
}

// ================= SMALL GEMM: CTA 128x64, 256 thr, K-chunk 128, NS=2 ========
// 8 warps in 2x4 grid, warp tile 64x16. Stage 48KB -> 96KB smem, 2 CTAs/SM.
#define A2_SUB   16384
#define A2_STAGE 32768
#define B2_SUB   8192
#define STAGE2   49152
#define SMEM2    (2*STAGE2)    // 98304
#define EPI2_P   68
#define EPI2_PT  132
#define NTHR2    256

template<int OP, bool OUTF, bool OUTB, bool TRANS>
__global__ void __launch_bounds__(NTHR2)
hmma_gemm_s(const h16* __restrict__ Ahi, const h16* __restrict__ Bhi,
            const float* __restrict__ bias,
            float* __restrict__ Cf, h16* __restrict__ Chi,
            int K, int ldC, size_t sA, size_t sB, size_t sC, float scale)
{
    extern __shared__ char smem[];
    const uint32_t sbase = smem_u32(smem);

    const int t = threadIdx.x;
    const int w = t >> 5, lane = t & 31;
    const int wm = w >> 2, wn = w & 3;            // warp grid 2 x 4

    const int bz = blockIdx.z;
    Ahi += (size_t)bz * sA;
    Bhi += (size_t)bz * sB;
    const int mBase = blockIdx.y * 128;
    const int nBase = blockIdx.x * 64;

    float accF[4][2][4];
    #pragma unroll
    for (int mi = 0; mi < 4; mi++)
        #pragma unroll
        for (int nj = 0; nj < 2; nj++)
            #pragma unroll
            for (int e = 0; e < 4; e++) accF[mi][nj][e] = 0.f;

    const int nk = K >> 7;

    const int arow = t >> 1;          // 0..127
    const uint32_t arx = ((uint32_t)(arow & 7)) << 4;
    const uint32_t arowoff = (uint32_t)arow * 128;
    const int brow = t >> 2;          // 0..63
    const uint32_t brx = ((uint32_t)(brow & 7)) << 4;
    const uint32_t browoff = (uint32_t)brow * 128;
    const size_t gArow = (size_t)(mBase + arow) * K;
    const size_t gBrow = (size_t)(nBase + brow) * K;

    auto ISSUE = [&](int kc, int s) {
        const int kb = kc << 7;
        const uint32_t st = sbase + (uint32_t)s * STAGE2;
        #pragma unroll
        for (int h = 0; h < 2; h++) {
            const int kh = kb + h * 64;
            #pragma unroll
            for (int c = 0; c < 4; c++) {
                const int col16 = (t & 1) * 4 + c;
                const uint32_t d = arowoff + (((uint32_t)col16 * 16) ^ arx);
                cpasync16(st + h * A2_SUB + d, Ahi + gArow + kh + col16 * 8);
            }
            #pragma unroll
            for (int c = 0; c < 2; c++) {
                const int col16 = (t & 3) * 2 + c;
                const uint32_t d = browoff + (((uint32_t)col16 * 16) ^ brx);
                cpasync16(st + A2_STAGE + h * B2_SUB + d, Bhi + gBrow + kh + col16 * 8);
            }
        }
    };

    const uint32_t arow128 = (uint32_t)(wm * 64 + (lane & 15)) * 128;
    const uint32_t a16     = ((uint32_t)(lane >> 4)) << 4;
    const uint32_t axor    = ((uint32_t)(lane & 7)) << 4;
    const uint32_t brow128 = (uint32_t)(wn * 16 + ((lane >> 4) << 3) + (lane & 7)) * 128;
    const uint32_t b16     = ((uint32_t)((lane >> 3) & 1)) << 4;

    auto COMPUTE = [&](int s) {
        const uint32_t st = sbase + (uint32_t)s * STAGE2;
        #pragma unroll
        for (int h = 0; h < 2; h++) {
            const uint32_t stA = st + h * A2_SUB;
            const uint32_t stB = st + A2_STAGE + h * B2_SUB;
            #pragma unroll
            for (int ki = 0; ki < 4; ki++) {
                const uint32_t kba = (uint32_t)(ki * 32);
                uint32_t Af[4][4], Bf[2][2];
                #pragma unroll
                for (int mi = 0; mi < 4; mi++)
                    ldsm4(Af[mi], stA + arow128 + mi * 2048 + ((kba + a16) ^ axor));
                {
                    uint32_t tb[4];
                    ldsm4(tb, stB + brow128 + ((kba + b16) ^ axor));
                    Bf[0][0] = tb[0]; Bf[0][1] = tb[1];
                    Bf[1][0] = tb[2]; Bf[1][1] = tb[3];
                }
                #pragma unroll
                for (int nj = 0; nj < 2; nj++)
                    #pragma unroll
                    for (int mi = 0; mi < 4; mi++)
                        mma_f32(accF[mi][nj], Af[mi], Bf[nj][0], Bf[nj][1]);
            }
        }
    };

    ISSUE(0, 0);
    CP_COMMIT();
    for (int kc = 0; kc < nk; kc++) {
        CP_WAIT(0);
        __syncthreads();
        if (kc + 1 < nk) { ISSUE(kc + 1, (kc + 1) & 1); CP_COMMIT(); }
        COMPUTE(kc & 1);
    }
    __syncthreads();

    float* epi = (float*)smem;
    const int g  = lane >> 2;
    const int tq = lane & 3;
    #pragma unroll
    for (int mi = 0; mi < 4; mi++) {
        #pragma unroll
        for (int nj = 0; nj < 2; nj++) {
            const int col = wn * 16 + nj * 8 + tq * 2;
            #pragma unroll
            for (int half = 0; half < 2; half++) {
                const int m = wm * 64 + mi * 16 + g + half * 8;
                float v0 = accF[mi][nj][half*2 + 0];
                float v1 = accF[mi][nj][half*2 + 1];
                if (OP == 2) {
                    v0 = 1.f / (1.f + __expf(-v0 * scale));
                    v1 = 1.f / (1.f + __expf(-v1 * scale));
                } else {
                    if (bias) { v0 += bias[nBase + col]; v1 += bias[nBase + col + 1]; }
                    if (OP == 1) { v0 = fmaxf(v0, 0.f); v1 = fmaxf(v1, 0.f); }
                }
                if (TRANS) {
                    epi[(col)     * EPI2_PT + m] = v0;
                    epi[(col + 1) * EPI2_PT + m] = v1;
                } else {
                    epi[m * EPI2_P + col]     = v0;
                    epi[m * EPI2_P + col + 1] = v1;
                }
            }
        }
    }
    __syncthreads();

    if (TRANS) {
        // epi holds [n(64)][m(128)]; write C^T[batch][nGlob][mGlob], ld = SEQ
        const int r  = t >> 2;            // 0..63
        const int ch = (t & 3) * 32;      // 0..96
        const size_t boffs = (size_t)(mBase >> 12) * ((size_t)EMB * SEQ);
        const size_t rowOff = boffs + (size_t)(nBase + r) * SEQ + (size_t)(mBase & (SEQ - 1)) + ch;
        #pragma unroll
        for (int i = 0; i < 8; i++) {
            const float* e = &epi[r * EPI2_PT + ch + i * 4];
            const float4 f = make_float4(e[0], e[1], e[2], e[3]);
            if (OUTF) *(float4*)(Cf + rowOff + i * 4) = f;
            if (OUTB) *(uint2*)(Chi + rowOff + i * 4) = h4cvt(f);
        }
    } else {
        const int r  = t >> 1;            // 0..127
        const int ch = (t & 1) * 32;
        const size_t rowOff = (size_t)bz * sC + (size_t)(mBase + r) * ldC + nBase + ch;
        #pragma unroll
        for (int i = 0; i < 8; i++) {
            const float* e = &epi[r * EPI2_P + ch + i * 4];
            const float4 f = make_float4(e[0], e[1], e[2], e[3]);
            if (OUTF) *(float4*)(Cf + rowOff + i * 4) = f;
            if (OUTB) *(uint2*)(Chi + rowOff + i * 4) = h4cvt(f);
        }
    }
}

// ---------------- LayerNorm ----------------
template<int BF>
__global__ void __launch_bounds__(256)
layernorm_kernel(const float* __restrict__ x, const float* __restrict__ g,
                 const float* __restrict__ b, float* __restrict__ outf,
                 h16* __restrict__ ohi)
{
    const int row = blockIdx.x;
    const float* xr = x + (size_t)row * EMB;
    const int t = threadIdx.x;

    const float4 v = *(const float4*)(xr + t * 4);
    float s  = v.x + v.y + v.z + v.w;
    float ss = v.x * v.x + v.y * v.y + v.z * v.z + v.w * v.w;

    __shared__ float shs[8], shss[8], shmu[1], shinv[1];
    const int lane = t & 31, w = t >> 5;
    #pragma unroll
    for (int o = 16; o > 0; o >>= 1) {
        s  += __shfl_down_sync(0xffffffffu, s,  o);
        ss += __shfl_down_sync(0xffffffffu, ss, o);
    }
    if (lane == 0) { shs[w] = s; shss[w] = ss; }
    __syncthreads();
    if (w == 0) {
        float s2  = (lane < 8) ? shs[lane]  : 0.f;
        float ss2 = (lane < 8) ? shss[lane] : 0.f;
        #pragma unroll
        for (int o = 4; o > 0; o >>= 1) {
            s2  += __shfl_down_sync(0xffffffffu, s2,  o);
            ss2 += __shfl_down_sync(0xffffffffu, ss2, o);
        }
        if (lane == 0) {
            const float mu  = s2 * (1.f / EMB);
            const float var = ss2 * (1.f / EMB) - mu * mu;
            shmu[0]  = mu;
            shinv[0] = rsqrtf(var + 1e-5f);
        }
    }
    __syncthreads();
    const float mu = shmu[0], inv = shinv[0];

    const float4 gv = *(const float4*)(g + t * 4);
    const float4 bv = *(const float4*)(b + t * 4);
    float4 o;
    o.x = (v.x - mu) * inv * gv.x + bv.x;
    o.y = (v.y - mu) * inv * gv.y + bv.y;
    o.z = (v.z - mu) * inv * gv.z + bv.z;
    o.w = (v.w - mu) * inv * gv.w + bv.w;
    const size_t off = (size_t)row * EMB + t * 4;
    if (BF == 0) {
        *(float4*)(outf + off) = o;
    } else {
        *(uint2*)(ohi + off) = h4cvt(o);
    }
}

// ---------------- launch ----------------
extern "C" void kernel_launch(void* const* d_in, const int* in_sizes, int n_in,
                              void* d_out, int out_size)
{
    const float* value  = (const float*)d_in[0];
    const float* key_t  = (const float*)d_in[1];
    const float* query  = (const float*)d_in[2];
    const float* embed0 = (const float*)d_in[3];
    const float* Wq = (const float*)d_in[4];
    const float* bq = (const float*)d_in[5];
    const float* Wk = (const float*)d_in[6];
    const float* bk = (const float*)d_in[7];
    const float* Wv = (const float*)d_in[8];
    const float* bv = (const float*)d_in[9];
    const float* W1 = (const float*)d_in[10];
    const float* b1 = (const float*)d_in[11];
    const float* W2 = (const float*)d_in[12];
    const float* b2 = (const float*)d_in[13];
    const float* g1  = (const float*)d_in[14];
    const float* be1 = (const float*)d_in[15];
    const float* g2  = (const float*)d_in[16];
    const float* be2 = (const float*)d_in[17];

    h16 *p_qinh, *p_kinh, *p_vinh;
    h16 *p_wqh, *p_wkh, *p_wvh, *p_w1h, *p_w2h;
    h16 *p_qh, *p_kh, *p_vth, *p_ath, *p_xh, *p_hh;
    float *p_attnf, *p_x, *p_y;
    cudaGetSymbolAddress((void**)&p_qinh, qin_h);
    cudaGetSymbolAddress((void**)&p_kinh, kin_h);
    cudaGetSymbolAddress((void**)&p_vinh, vin_h);
    cudaGetSymbolAddress((void**)&p_wqh, wq_h);
    cudaGetSymbolAddress((void**)&p_wkh, wk_h);
    cudaGetSymbolAddress((void**)&p_wvh, wv_h);
    cudaGetSymbolAddress((void**)&p_w1h, w1_h);
    cudaGetSymbolAddress((void**)&p_w2h, w2_h);
    cudaGetSymbolAddress((void**)&p_qh, q_h);
    cudaGetSymbolAddress((void**)&p_kh, k_h);
    cudaGetSymbolAddress((void**)&p_vth, vt_h);
    cudaGetSymbolAddress((void**)&p_ath, at_h);
    cudaGetSymbolAddress((void**)&p_xh, x_h);
    cudaGetSymbolAddress((void**)&p_hh, h_h);
    cudaGetSymbolAddress((void**)&p_attnf, g_attnf);
    cudaGetSymbolAddress((void**)&p_x, g_x);
    cudaGetSymbolAddress((void**)&p_y, g_y);

    #define SET_SMEM(KER, SZ) cudaFuncSetAttribute(KER, cudaFuncAttributeMaxDynamicSharedMemorySize, SZ)
    SET_SMEM((hmma_gemm<2,true,true,false>),  SMEM_TOTAL);   // attn (fp32 + fp16)
    SET_SMEM((hmma_gemm<1,false,true,false>), SMEM_TOTAL);   // FFN1 relu fp16 out
    SET_SMEM((hmma_gemm_s<0,false,true,false>), SMEM2);      // q/k fp16 out
    SET_SMEM((hmma_gemm_s<0,false,true,true>),  SMEM2);      // vt trans fp16 out
    SET_SMEM((hmma_gemm_s<0,true,false,false>), SMEM2);      // fp32 out (attnV / FFN2)

    float* outp = (float*)d_out;
    const long long outElems  = (long long)MROWS * EMB;
    const long long attnElems = (long long)NBATCH * SEQ * SEQ;
    float* attnf = ((long long)out_size >= outElems + attnElems) ? (outp + outElems) : p_attnf;

    dim3 blk(NTHR);
    dim3 blk2(NTHR2);
    dim3 blkc(256);
    const float scale = 1.0f / 32.0f;
    const size_t sQK = (size_t)SEQ * EMB;
    const size_t sAT = (size_t)SEQ * SEQ;
    const size_t sVT = (size_t)EMB * SEQ;

    // 0) input/weight conversions
    cvt_h<<<MROWS*EMB/1024, blkc>>>(query, embed0, p_qinh);
    cvt_h<<<MROWS*EMB/1024, blkc>>>(key_t, embed0, p_kinh);
    cvt_h<<<MROWS*EMB/1024, blkc>>>(value, embed0, p_vinh);
    cvt_h<<<EMB*EMB/1024,   blkc>>>(Wq, nullptr, p_wqh);
    cvt_h<<<EMB*EMB/1024,   blkc>>>(Wk, nullptr, p_wkh);
    cvt_h<<<EMB*EMB/1024,   blkc>>>(Wv, nullptr, p_wvh);
    cvt_h<<<FFDIM*EMB/1024, blkc>>>(W1, nullptr, p_w1h);
    cvt_h<<<EMB*FFDIM/1024, blkc>>>(W2, nullptr, p_w2h);

    // 1) QKV projections — small tiles (1024 CTAs each)
    dim3 gQKV(EMB / 64, MROWS / 128, 1);
    hmma_gemm_s<0,false,true,false><<<gQKV, blk2, SMEM2>>>(
        p_qinh, p_wqh, bq, nullptr, p_qh, EMB, EMB, 0, 0, 0, 0.f);
    hmma_gemm_s<0,false,true,false><<<gQKV, blk2, SMEM2>>>(
        p_kinh, p_wkh, bk, nullptr, p_kh, EMB, EMB, 0, 0, 0, 0.f);
    hmma_gemm_s<0,false,true,true><<<gQKV, blk2, SMEM2>>>(
        p_vinh, p_wvh, bv, nullptr, p_vth, EMB, SEQ, 0, 0, 0, 0.f);

    // 2) attn = sigmoid(q @ k^T * scale) — big tiles (1024 CTAs)
    dim3 gS(SEQ / 128, SEQ / 256, NBATCH);
    hmma_gemm<2,true,true,false><<<gS, blk, SMEM_TOTAL>>>(
        p_qh, p_kh, nullptr, attnf, p_ath, EMB, SEQ, sQK, sQK, sAT, scale);

    // 3) x = attn @ v — small tiles (1024 CTAs)
    dim3 gAV(EMB / 64, SEQ / 128, NBATCH);
    hmma_gemm_s<0,true,false,false><<<gAV, blk2, SMEM2>>>(
        p_ath, p_vth, nullptr, p_x, nullptr, SEQ, EMB, sAT, sVT, sQK, 0.f);

    // 4) LN1 -> fp16
    layernorm_kernel<1><<<MROWS, 256>>>(p_x, g1, be1, nullptr, p_xh);

    // 5) FFN1 = relu(x @ W1^T + b1) -> fp16 — big tiles (1024 CTAs)
    dim3 gF1(FFDIM / 128, MROWS / 256, 1);
    hmma_gemm<1,false,true,false><<<gF1, blk, SMEM_TOTAL>>>(
        p_xh, p_w1h, b1, nullptr, p_hh, EMB, FFDIM, 0, 0, 0, 0.f);

    // 6) FFN2 = h @ W2^T + b2 -> fp32 — small tiles (1024 CTAs)
    dim3 gF2(EMB / 64, MROWS / 128, 1);
    hmma_gemm_s<0,true,false,false><<<gF2, blk2, SMEM2>>>(
        p_hh, p_w2h, b2, p_y, nullptr, FFDIM, EMB, 0, 0, 0, 0.f);

    // 7) LN2 -> out
    layernorm_kernel<0><<<MROWS, 256>>>(p_y, g2, be2, outp, nullptr);
}